// round 14
// baseline (speedup 1.0000x reference)
#include <cuda_runtime.h>
#include <cuda_fp16.h>
#include <math.h>
#include <stdint.h>

#define NN    100000
#define NE    1600000
#define NG    64
#define CATC  128
#define NHEAD 4
#define OUTD  64
#define EPSN  1e-5f
#define SLOPE 0.2f
#define SCAN_B ((NN + 1023) / 1024)   // 98
#define GEMMB ((NN + 127) / 128)      // 782
#define EDGE4B ((NE / 4 + 255) / 256) // 1563

// ---------------- scratch (device globals) ----------------
__device__ float   g_bufX[NN * CATC];
__device__ __half2 g_bufH16[NN * 64];
__device__ float   g_ssrc[NN * NHEAD];
__device__ float   g_sdst[NN * NHEAD];
__device__ float   g_maxs[NHEAD];
__device__ float   g_maxd[NHEAD];
__device__ float   g_nA[NG * CATC];
__device__ float   g_nB[NG * CATC];
__device__ float   g_pool[NG * CATC];
__device__ int     g_start[NG + 2];
__device__ int     g_cnt[NN];
__device__ int     g_off[NN + 1];
__device__ int     g_cursor[NN];
__device__ int     g_bsum[SCAN_B];
__device__ int     g_boff[SCAN_B];
__device__ int     g_csr[NE];
__device__ uint4   g_wfrag[3 * 16 * 16 * 32];  // [layer][ntG][ktG][lane]

__device__ __forceinline__ float lrelu(float x) { return x > 0.f ? x : SLOPE * x; }
__device__ __forceinline__ float eluf(float x)  { return x > 0.f ? x : __expf(x) - 1.f; }

__device__ __forceinline__ void atomicMaxF(float* a, float v) {
    if (v >= 0.f) atomicMax((int*)a, __float_as_int(v));
    else          atomicMin((unsigned int*)a, __float_as_uint(v));
}

__device__ __forceinline__ uint32_t tf32rn(float x) {
    uint32_t r;
    asm("cvt.rna.tf32.f32 %0, %1;" : "=r"(r) : "f"(x));
    return r;
}
__device__ __forceinline__ void mma8(float* d, uint32_t a0, uint32_t a1,
                                     uint32_t a2, uint32_t a3,
                                     uint32_t b0, uint32_t b1) {
    asm volatile(
        "mma.sync.aligned.m16n8k8.row.col.f32.tf32.tf32.f32 "
        "{%0,%1,%2,%3}, {%4,%5,%6,%7}, {%8,%9}, {%0,%1,%2,%3};"
        : "+f"(d[0]), "+f"(d[1]), "+f"(d[2]), "+f"(d[3])
        : "r"(a0), "r"(a1), "r"(a2), "r"(a3), "r"(b0), "r"(b1));
}

// ---------------- all W -> fragments (once) ----------------
__global__ void k_wconv3(const float* __restrict__ w0,
                         const float* __restrict__ w1,
                         const float* __restrict__ w2) {
    int idx = blockIdx.x * blockDim.x + threadIdx.x;
    if (idx >= 3 * 8192) return;
    int l = idx >> 13, s = idx & 8191;
    const float* W = (l == 0) ? w0 : (l == 1) ? w1 : w2;
    int lane = s & 31, ktG = (s >> 5) & 15, ntG = s >> 9;
    int n = ntG * 8 + (lane >> 2);
    int k0 = ktG * 8 + (lane & 3);
    float v0 = W[n * CATC + k0];
    float v1 = W[n * CATC + k0 + 4];
    uint4 f;
    f.x = tf32rn(v0);
    f.y = tf32rn(v1);
    f.z = tf32rn(v0 - __uint_as_float(f.x));
    f.w = tf32rn(v1 - __uint_as_float(f.y));
    g_wfrag[idx] = f;
}

// ------ TF32 tensor GEMM, 2-pass split (+bias)(+scores+max)(+norm)(+CSR tails) ---
// TAIL: 0 = none, 1 = degree-count tail, 2 = csr-fill tail
#define TG_SMEM ((128 * 132 + 384) * 4)

template <int ASEL, int DSEL, int WSEL, bool BIAS, bool SCORES, bool NORM, int TAIL>
__global__ void __launch_bounds__(256, 2)
k_tgemm(const float* __restrict__ Aext,
        const float* __restrict__ bias,
        const float* __restrict__ a_src,
        const float* __restrict__ a_dst,
        const int* __restrict__ batch,
        const int* __restrict__ ei) {
    extern __shared__ float sm[];
    int tid = threadIdx.x;

    // -------- CSR tail blocks (atomic-latency work hidden under GEMM) --------
    if (TAIL != 0) {
        int tb = (int)blockIdx.x - GEMMB;
        if (tb >= 0) {
            int t = tb * 256 + tid;
            if (t < NE / 4) {
                if (TAIL == 1) {
                    int4 d4 = ((const int4*)(ei + NE))[t];
                    atomicAdd(&g_cnt[d4.x], 1);
                    atomicAdd(&g_cnt[d4.y], 1);
                    atomicAdd(&g_cnt[d4.z], 1);
                    atomicAdd(&g_cnt[d4.w], 1);
                } else {
                    int4 s4 = ((const int4*)ei)[t];
                    int4 d4 = ((const int4*)(ei + NE))[t];
                    g_csr[atomicAdd(&g_cursor[d4.x], 1)] = s4.x;
                    g_csr[atomicAdd(&g_cursor[d4.y], 1)] = s4.y;
                    g_csr[atomicAdd(&g_cursor[d4.z], 1)] = s4.z;
                    g_csr[atomicAdd(&g_cursor[d4.w], 1)] = s4.w;
                }
            }
            return;
        }
    }

    float* aT   = sm;                  // [128][132]
    float* sBia = sm + 128 * 132;
    float* sSrc = sBia + 128;
    float* sDst = sSrc + 128;

    const float* A = (ASEL == 0) ? Aext : g_bufX;

    int wid = tid >> 5, lane = tid & 31;
    int wm = wid >> 1, wn = wid & 1, gid = lane >> 2, tig = lane & 3;
    int row0 = blockIdx.x * 128;

    if (tid < 128) {
        if (BIAS) sBia[tid] = bias[tid];
        if (SCORES) { sSrc[tid] = a_src[tid]; sDst[tid] = a_dst[tid]; }
    }

#pragma unroll
    for (int i = 0; i < 16; i++) {
        int idx = tid + 256 * i;
        int r = idx >> 5, q = idx & 31;
        int grow = row0 + r;
        float4 v = make_float4(0.f, 0.f, 0.f, 0.f);
        if (grow < NN) {
            v = ((const float4*)A)[grow * 32 + q];
            if (NORM) {
                int g = batch[grow];
                float4 a4 = ((const float4*)g_nA)[g * 32 + q];
                float4 b4 = ((const float4*)g_nB)[g * 32 + q];
                v.x = fmaf(v.x, a4.x, b4.x);
                v.y = fmaf(v.y, a4.y, b4.y);
                v.z = fmaf(v.z, a4.z, b4.z);
                v.w = fmaf(v.w, a4.w, b4.w);
            }
        }
        *(float4*)&aT[r * 132 + q * 4] = v;
    }
    __syncthreads();

    float d[2][8][4];
#pragma unroll
    for (int mt = 0; mt < 2; mt++)
#pragma unroll
        for (int nt = 0; nt < 8; nt++)
#pragma unroll
            for (int f = 0; f < 4; f++) d[mt][nt][f] = 0.f;

    const uint4* wf = g_wfrag + WSEL * 8192;

#pragma unroll 4
    for (int ktG = 0; ktG < 16; ktG++) {
        uint4 bb[8];
#pragma unroll
        for (int nt = 0; nt < 8; nt++)
            bb[nt] = wf[(((wn * 8 + nt) << 4) + ktG) * 32 + lane];
        // A fragments: hi only (2-pass split; aL*b term dropped, ~2.8e-4 rel RMS)
        uint32_t aH[2][4];
#pragma unroll
        for (int mt = 0; mt < 2; mt++) {
            int rb = wm * 32 + mt * 16 + gid;
            int c = ktG * 8 + tig;
            aH[mt][0] = tf32rn(aT[rb * 132 + c]);
            aH[mt][1] = tf32rn(aT[(rb + 8) * 132 + c]);
            aH[mt][2] = tf32rn(aT[rb * 132 + c + 4]);
            aH[mt][3] = tf32rn(aT[(rb + 8) * 132 + c + 4]);
        }
#pragma unroll
        for (int nt = 0; nt < 8; nt++)
#pragma unroll
            for (int mt = 0; mt < 2; mt++) {
                mma8(d[mt][nt], aH[mt][0], aH[mt][1], aH[mt][2], aH[mt][3], bb[nt].x, bb[nt].y);
                mma8(d[mt][nt], aH[mt][0], aH[mt][1], aH[mt][2], aH[mt][3], bb[nt].z, bb[nt].w);
            }
    }

    // epilogue: store (fp32 encoder / fp16 layers) + fused scores + fused max
    float sc[2][2][2][2];
    if (SCORES) {
#pragma unroll
        for (int a = 0; a < 2; a++)
#pragma unroll
            for (int b = 0; b < 2; b++)
#pragma unroll
                for (int c = 0; c < 2; c++) {
                    sc[a][b][c][0] = 0.f; sc[a][b][c][1] = 0.f;
                }
    }
#pragma unroll
    for (int mt = 0; mt < 2; mt++) {
        int r0 = row0 + wm * 32 + mt * 16 + gid;
#pragma unroll
        for (int nt = 0; nt < 8; nt++) {
            int c0 = wn * 64 + nt * 8 + 2 * tig;
            float v0 = d[mt][nt][0], v1 = d[mt][nt][1];
            float v2 = d[mt][nt][2], v3 = d[mt][nt][3];
            if (SCORES) {
                int hh = nt >> 2;
                float s0 = sSrc[c0], s1 = sSrc[c0 + 1];
                float t0 = sDst[c0], t1 = sDst[c0 + 1];
                sc[mt][0][hh][0] += v0 * s0 + v1 * s1;
                sc[mt][0][hh][1] += v0 * t0 + v1 * t1;
                sc[mt][1][hh][0] += v2 * s0 + v3 * s1;
                sc[mt][1][hh][1] += v2 * t0 + v3 * t1;
            }
            if (BIAS) {
                float b0 = sBia[c0], b1 = sBia[c0 + 1];
                v0 += b0; v1 += b1; v2 += b0; v3 += b1;
            }
            if (r0 < NN) {
                if (DSEL == 0) *(float2*)&g_bufX[r0 * CATC + c0] = make_float2(v0, v1);
                else           g_bufH16[r0 * 64 + (c0 >> 1)] = __floats2half2_rn(v0, v1);
            }
            if (r0 + 8 < NN) {
                if (DSEL == 0) *(float2*)&g_bufX[(r0 + 8) * CATC + c0] = make_float2(v2, v3);
                else           g_bufH16[(r0 + 8) * 64 + (c0 >> 1)] = __floats2half2_rn(v2, v3);
            }
        }
    }
    if (SCORES) {
#pragma unroll
        for (int a = 0; a < 2; a++)
#pragma unroll
            for (int b = 0; b < 2; b++)
#pragma unroll
                for (int c = 0; c < 2; c++)
#pragma unroll
                    for (int s = 0; s < 2; s++) {
                        float v = sc[a][b][c][s];
                        v += __shfl_xor_sync(0xffffffffu, v, 1);
                        v += __shfl_xor_sync(0xffffffffu, v, 2);
                        sc[a][b][c][s] = v;
                    }
        if (tig == 0) {
#pragma unroll
            for (int mt = 0; mt < 2; mt++)
#pragma unroll
                for (int rh = 0; rh < 2; rh++) {
                    int r = row0 + wm * 32 + mt * 16 + gid + rh * 8;
                    if (r < NN) {
#pragma unroll
                        for (int hh = 0; hh < 2; hh++) {
                            int head = wn * 2 + hh;
                            g_ssrc[r * 4 + head] = sc[mt][rh][hh][0];
                            g_sdst[r * 4 + head] = sc[mt][rh][hh][1];
                        }
                    }
                }
        }
        // fused per-head global max (padded rows add score 0 — softmax
        // shift-invariance makes any finite upper bound valid)
#pragma unroll
        for (int hh = 0; hh < 2; hh++) {
            float ms = fmaxf(fmaxf(sc[0][0][hh][0], sc[0][1][hh][0]),
                             fmaxf(sc[1][0][hh][0], sc[1][1][hh][0]));
            float md = fmaxf(fmaxf(sc[0][0][hh][1], sc[0][1][hh][1]),
                             fmaxf(sc[1][0][hh][1], sc[1][1][hh][1]));
#pragma unroll
            for (int off = 4; off <= 16; off <<= 1) {
                ms = fmaxf(ms, __shfl_xor_sync(0xffffffffu, ms, off));
                md = fmaxf(md, __shfl_xor_sync(0xffffffffu, md, off));
            }
            if (lane == 0) {
                atomicMaxF(&g_maxs[wn * 2 + hh], ms);
                atomicMaxF(&g_maxd[wn * 2 + hh], md);
            }
        }
    }
}

// ---------------- pre: zero counts + preset g_start + max init ----------------
__global__ void k_pre() {
    int i = blockIdx.x * blockDim.x + threadIdx.x;
    if (i < NN) g_cnt[i] = 0;
    if (i <= NG) g_start[i] = NN;
    if (i < NHEAD) {
        g_maxs[i] = __int_as_float(0xff800000u);
        g_maxd[i] = __int_as_float(0xff800000u);
    }
}
__global__ void k_start_fill(const int* __restrict__ batch) {
    int i = blockIdx.x * blockDim.x + threadIdx.x;
    if (i >= NN) return;
    int b = batch[i];
    int bp = (i == 0) ? -1 : batch[i - 1];
    for (int g = bp + 1; g <= b; ++g) g_start[g] = i;
}
__global__ void k_scan1() {
    __shared__ int wsum[8];
    int b = blockIdx.x, t = threadIdx.x;
    int idx0 = b * 1024 + t * 4;
    int v[4];
#pragma unroll
    for (int k = 0; k < 4; k++) v[k] = (idx0 + k < NN) ? g_cnt[idx0 + k] : 0;
    int s = v[0] + v[1] + v[2] + v[3];
    int lane = t & 31, wid = t >> 5;
    int incl = s;
#pragma unroll
    for (int off = 1; off <= 16; off <<= 1) {
        int nv = __shfl_up_sync(0xffffffffu, incl, off);
        if (lane >= off) incl += nv;
    }
    if (lane == 31) wsum[wid] = incl;
    __syncthreads();
    if (t == 0) {
        int r = 0;
#pragma unroll
        for (int w = 0; w < 8; w++) { int x = wsum[w]; wsum[w] = r; r += x; }
    }
    __syncthreads();
    int excl = incl - s + wsum[wid];
    int run = excl;
#pragma unroll
    for (int k = 0; k < 4; k++) {
        if (idx0 + k < NN) g_off[idx0 + k] = run;
        run += v[k];
    }
    if (t == 255) g_bsum[b] = excl + s;
}
__global__ void k_scan2() {
    int r = 0;
    for (int b = 0; b < SCAN_B; b++) { g_boff[b] = r; r += g_bsum[b]; }
    g_off[NN] = r;
}
__global__ void k_scan3() {
    int i = blockIdx.x * blockDim.x + threadIdx.x;
    if (i >= NN) return;
    int o = g_off[i] + g_boff[i >> 10];
    g_off[i] = o;
    g_cursor[i] = o;
}

// ---------------- reset per-head maxima between layers ----------------
__global__ void k_shift_init() {
    if (threadIdx.x < NHEAD) {
        g_maxs[threadIdx.x] = __int_as_float(0xff800000u);
        g_maxd[threadIdx.x] = __int_as_float(0xff800000u);
    }
}

// ---------------- fused GAT aggregate (warp per dst, fp16 gather) ----------------
__global__ void k_gat(const float* __restrict__ bias) {
    int n = (blockIdx.x * blockDim.x + threadIdx.x) >> 5;
    if (n >= NN) return;
    int lane = threadIdx.x & 31;
    int head = lane >> 3;

    float shift = lrelu(g_maxs[head] + g_maxd[head]);
    float sd = g_sdst[n * 4 + head];

    // self-loop (fp16 h)
    float p = __expf(lrelu(g_ssrc[n * 4 + head] + sd) - shift);
    uint2 hs = ((const uint2*)g_bufH16)[n * 32 + lane];
    float2 s01 = __half22float2(*(__half2*)&hs.x);
    float2 s23 = __half22float2(*(__half2*)&hs.y);
    float ax = s01.x * p, ay = s01.y * p, az = s23.x * p, aw = s23.y * p;
    float den = p;

    int o0 = g_off[n], o1 = g_off[n + 1];
    for (int base = o0; base < o1; base += 32) {
        int id = 0;
        if (base + lane < o1) id = g_csr[base + lane];
        int cnt = min(32, o1 - base);
#pragma unroll 4
        for (int j = 0; j < cnt; j++) {
            int src = __shfl_sync(0xffffffffu, id, j);
            float ss = g_ssrc[src * 4 + head];
            float pe = __expf(lrelu(ss + sd) - shift);
            uint2 hraw = ((const uint2*)g_bufH16)[src * 32 + lane];
            float2 f01 = __half22float2(*(__half2*)&hraw.x);
            float2 f23 = __half22float2(*(__half2*)&hraw.y);
            ax += f01.x * pe; ay += f01.y * pe;
            az += f23.x * pe; aw += f23.y * pe;
            den += pe;
        }
    }
    float inv = 1.f / den;
    float4 b = ((const float4*)bias)[lane];
    float4 o;
    o.x = eluf(ax * inv + b.x);
    o.y = eluf(ay * inv + b.y);
    o.z = eluf(az * inv + b.z);
    o.w = eluf(aw * inv + b.w);
    ((float4*)g_bufX)[n * 32 + lane] = o;
}

// ---------------- GraphNorm stats -> affine A',B' ----------------
__global__ void k_norm_stats(const float* __restrict__ nw,
                             const float* __restrict__ nb,
                             const float* __restrict__ nms) {
    __shared__ float sh[256], sh2[256];
    int g = blockIdx.x, q = blockIdx.y;
    int tc = threadIdx.x & 31, tr = threadIdx.x >> 5;
    int c = q * 32 + tc;
    int s0 = g_start[g], s1 = g_start[g + 1];
    float s = 0.f, s2 = 0.f;
    for (int r = s0 + tr; r < s1; r += 8) {
        float v = g_bufX[r * CATC + c];
        s += v; s2 += v * v;
    }
    sh[threadIdx.x] = s; sh2[threadIdx.x] = s2;
    __syncthreads();
    for (int off = 128; off >= 32; off >>= 1) {
        if (threadIdx.x < off) {
            sh[threadIdx.x] += sh[threadIdx.x + off];
            sh2[threadIdx.x] += sh2[threadIdx.x + off];
        }
        __syncthreads();
    }
    if (threadIdx.x < 32) {
        int cnt = s1 - s0;
        float A = 0.f, B = nb[c];
        if (cnt > 0) {
            float fc = (float)cnt;
            float mean = sh[tc] / fc;
            float ms = nms[c];
            float var = sh2[tc] / fc - (2.f * ms - ms * ms) * mean * mean;
            float inv = rsqrtf(var + EPSN);
            A = nw[c] * inv;
            B = nb[c] - A * ms * mean;
        }
        g_nA[g * CATC + c] = A;
        g_nB[g * CATC + c] = B;
    }
}

// ---------------- global max pool (+fused norm2 affine) ----------------
__global__ void k_pool() {
    __shared__ float sh[256];
    int g = blockIdx.x, q = blockIdx.y;
    int tc = threadIdx.x & 31, tr = threadIdx.x >> 5;
    int c = q * 32 + tc;
    int s0 = g_start[g], s1 = g_start[g + 1];
    float a = g_nA[g * CATC + c], b = g_nB[g * CATC + c];
    float m = __int_as_float(0xff800000u);
    for (int r = s0 + tr; r < s1; r += 8)
        m = fmaxf(m, fmaf(g_bufX[r * CATC + c], a, b));
    sh[threadIdx.x] = m;
    __syncthreads();
    for (int off = 128; off >= 32; off >>= 1) {
        if (threadIdx.x < off) sh[threadIdx.x] = fmaxf(sh[threadIdx.x], sh[threadIdx.x + off]);
        __syncthreads();
    }
    if (threadIdx.x < 32) g_pool[g * CATC + c] = sh[tc];
}

// ---------------- final fc ----------------
__global__ void k_fc(const float* __restrict__ fw, const float* __restrict__ fb,
                     float* __restrict__ out) {
    int g = blockIdx.x, o = threadIdx.x;
    float acc = fb[o];
#pragma unroll
    for (int c = 0; c < CATC; c += 4) {
        float4 p  = *(const float4*)&g_pool[g * CATC + c];
        float4 wv = *(const float4*)&fw[o * CATC + c];
        acc += p.x * wv.x + p.y * wv.y + p.z * wv.z + p.w * wv.w;
    }
    out[g * OUTD + o] = acc;
}

// ---------------- launch ----------------
extern "C" void kernel_launch(void* const* d_in, const int* in_sizes, int n_in,
                              void* d_out, int out_size) {
    const float* x     = (const float*)d_in[0];
    const int*   ei    = (const int*)d_in[1];
    const int*   batch = (const int*)d_in[2];
    const float* enc_w = (const float*)d_in[3];
    const float* enc_b = (const float*)d_in[4];
    const float* w1    = (const float*)d_in[5];
    const float* as1   = (const float*)d_in[6];
    const float* ad1   = (const float*)d_in[7];
    const float* b1    = (const float*)d_in[8];
    const float* n1w   = (const float*)d_in[9];
    const float* n1b   = (const float*)d_in[10];
    const float* n1ms  = (const float*)d_in[11];
    const float* w2    = (const float*)d_in[12];
    const float* as2   = (const float*)d_in[13];
    const float* ad2   = (const float*)d_in[14];
    const float* b2    = (const float*)d_in[15];
    const float* n2w   = (const float*)d_in[16];
    const float* n2b   = (const float*)d_in[17];
    const float* n2ms  = (const float*)d_in[18];
    const float* fw    = (const float*)d_in[19];
    const float* fb    = (const float*)d_in[20];
    float* out = (float*)d_out;

    cudaFuncSetAttribute(k_tgemm<0, 0, 0, true, false, false, 1>,
                         cudaFuncAttributeMaxDynamicSharedMemorySize, TG_SMEM);
    cudaFuncSetAttribute(k_tgemm<1, 1, 1, false, true, false, 2>,
                         cudaFuncAttributeMaxDynamicSharedMemorySize, TG_SMEM);
    cudaFuncSetAttribute(k_tgemm<1, 1, 2, false, true, true, 0>,
                         cudaFuncAttributeMaxDynamicSharedMemorySize, TG_SMEM);

    const int gatBlocks = (NN * 32 + 255) / 256;

    // prep (counts zeroed, g_start preset, maxima init for layer 1, W fragments)
    k_pre<<<(NN + 255) / 256, 256>>>();
    k_start_fill<<<(NN + 255) / 256, 256>>>(batch);
    k_wconv3<<<96, 256>>>(enc_w, w1, w2);

    // encoder GEMM + degree-count tail blocks (overlapped)
    k_tgemm<0, 0, 0, true, false, false, 1><<<GEMMB + EDGE4B, 256, TG_SMEM>>>(
        x, enc_b, nullptr, nullptr, nullptr, ei);

    // prefix scan (needs degrees)
    k_scan1<<<SCAN_B, 256>>>();
    k_scan2<<<1, 1>>>();
    k_scan3<<<(NN + 255) / 256, 256>>>();

    // ---- layer 1 GEMM (scores + fused max) + CSR-fill tail blocks ----
    k_tgemm<1, 1, 1, false, true, false, 2><<<GEMMB + EDGE4B, 256, TG_SMEM>>>(
        nullptr, nullptr, as1, ad1, nullptr, ei);
    k_gat<<<gatBlocks, 256>>>(b1);
    k_norm_stats<<<dim3(NG, 4), 256>>>(n1w, n1b, n1ms);

    // ---- layer 2 (A-staging applies norm1 affine; maxima reset first) ----
    k_shift_init<<<1, 32>>>();
    k_tgemm<1, 1, 2, false, true, true, 0><<<GEMMB, 256, TG_SMEM>>>(
        nullptr, nullptr, as2, ad2, batch, nullptr);
    k_gat<<<gatBlocks, 256>>>(b2);
    k_norm_stats<<<dim3(NG, 4), 256>>>(n2w, n2b, n2ms);

    // ---- pool (applies norm2 affine) + fc ----
    k_pool<<<dim3(NG, 4), 256>>>();
    k_fc<<<NG, OUTD>>>(fw, fb, out);
}

// round 15
// speedup vs baseline: 1.3033x; 1.3033x over previous
#include <cuda_runtime.h>
#include <cuda_fp16.h>
#include <math.h>
#include <stdint.h>

#define NN    100000
#define NE    1600000
#define NG    64
#define CATC  128
#define NHEAD 4
#define OUTD  64
#define EPSN  1e-5f
#define SLOPE 0.2f
#define SCAN_B ((NN + 1023) / 1024)   // 98
#define GEMMB ((NN + 127) / 128)      // 782
#define EDGE4B ((NE / 4 + 255) / 256) // 1563

// ---------------- scratch (device globals) ----------------
__device__ float   g_bufX[NN * CATC];
__device__ __half2 g_bufH16[NN * 64];
__device__ float   g_ssrc[NN * NHEAD];
__device__ float   g_sdst[NN * NHEAD];
__device__ float   g_maxs[NHEAD];
__device__ float   g_maxd[NHEAD];
__device__ float   g_nA[NG * CATC];
__device__ float   g_nB[NG * CATC];
__device__ float   g_pool[NG * CATC];
__device__ int     g_start[NG + 2];
__device__ int     g_cnt[NN];
__device__ int     g_off[NN + 1];
__device__ int     g_cursor[NN];
__device__ int     g_bsum[SCAN_B];
__device__ int     g_boff[SCAN_B];
__device__ int     g_csr[NE];
__device__ uint4   g_wfrag[3 * 16 * 16 * 32];  // [layer][ntG][ktG][lane]

__device__ __forceinline__ float lrelu(float x) { return x > 0.f ? x : SLOPE * x; }
__device__ __forceinline__ float eluf(float x)  { return x > 0.f ? x : __expf(x) - 1.f; }

__device__ __forceinline__ void atomicMaxF(float* a, float v) {
    if (v >= 0.f) atomicMax((int*)a, __float_as_int(v));
    else          atomicMin((unsigned int*)a, __float_as_uint(v));
}

__device__ __forceinline__ uint32_t tf32rn(float x) {
    uint32_t r;
    asm("cvt.rna.tf32.f32 %0, %1;" : "=r"(r) : "f"(x));
    return r;
}
__device__ __forceinline__ void mma8(float* d, uint32_t a0, uint32_t a1,
                                     uint32_t a2, uint32_t a3,
                                     uint32_t b0, uint32_t b1) {
    asm volatile(
        "mma.sync.aligned.m16n8k8.row.col.f32.tf32.tf32.f32 "
        "{%0,%1,%2,%3}, {%4,%5,%6,%7}, {%8,%9}, {%0,%1,%2,%3};"
        : "+f"(d[0]), "+f"(d[1]), "+f"(d[2]), "+f"(d[3])
        : "r"(a0), "r"(a1), "r"(a2), "r"(a3), "r"(b0), "r"(b1));
}

// ---------------- all W -> fragments (once) ----------------
__global__ void k_wconv3(const float* __restrict__ w0,
                         const float* __restrict__ w1,
                         const float* __restrict__ w2) {
    int idx = blockIdx.x * blockDim.x + threadIdx.x;
    if (idx >= 3 * 8192) return;
    int l = idx >> 13, s = idx & 8191;
    const float* W = (l == 0) ? w0 : (l == 1) ? w1 : w2;
    int lane = s & 31, ktG = (s >> 5) & 15, ntG = s >> 9;
    int n = ntG * 8 + (lane >> 2);
    int k0 = ktG * 8 + (lane & 3);
    float v0 = W[n * CATC + k0];
    float v1 = W[n * CATC + k0 + 4];
    uint4 f;
    f.x = tf32rn(v0);
    f.y = tf32rn(v1);
    f.z = tf32rn(v0 - __uint_as_float(f.x));
    f.w = tf32rn(v1 - __uint_as_float(f.y));
    g_wfrag[idx] = f;
}

// ------ TF32 tensor GEMM 3xTF32 (+bias)(+scores+max)(+norm)(+CSR tails) ---------
// TAIL: 0 = none, 1 = degree-count tail, 2 = csr-fill tail
#define TG_SMEM ((128 * 132 + 384) * 4)

template <int ASEL, int DSEL, int WSEL, bool BIAS, bool SCORES, bool NORM, int TAIL>
__global__ void __launch_bounds__(256, 2)
k_tgemm(const float* __restrict__ Aext,
        const float* __restrict__ bias,
        const float* __restrict__ a_src,
        const float* __restrict__ a_dst,
        const int* __restrict__ batch,
        const int* __restrict__ ei) {
    extern __shared__ float sm[];
    int tid = threadIdx.x;

    // -------- CSR tail blocks (atomic-latency work hidden under GEMM) --------
    if (TAIL != 0) {
        int tb = (int)blockIdx.x - GEMMB;
        if (tb >= 0) {
            int t = tb * 256 + tid;
            if (t < NE / 4) {
                if (TAIL == 1) {
                    int4 d4 = ((const int4*)(ei + NE))[t];
                    atomicAdd(&g_cnt[d4.x], 1);
                    atomicAdd(&g_cnt[d4.y], 1);
                    atomicAdd(&g_cnt[d4.z], 1);
                    atomicAdd(&g_cnt[d4.w], 1);
                } else {
                    int4 s4 = ((const int4*)ei)[t];
                    int4 d4 = ((const int4*)(ei + NE))[t];
                    g_csr[atomicAdd(&g_cursor[d4.x], 1)] = s4.x;
                    g_csr[atomicAdd(&g_cursor[d4.y], 1)] = s4.y;
                    g_csr[atomicAdd(&g_cursor[d4.z], 1)] = s4.z;
                    g_csr[atomicAdd(&g_cursor[d4.w], 1)] = s4.w;
                }
            }
            return;
        }
    }

    float* aT   = sm;                  // [128][132]
    float* sBia = sm + 128 * 132;
    float* sSrc = sBia + 128;
    float* sDst = sSrc + 128;

    const float* A = (ASEL == 0) ? Aext : g_bufX;

    int wid = tid >> 5, lane = tid & 31;
    int wm = wid >> 1, wn = wid & 1, gid = lane >> 2, tig = lane & 3;
    int row0 = blockIdx.x * 128;

    if (tid < 128) {
        if (BIAS) sBia[tid] = bias[tid];
        if (SCORES) { sSrc[tid] = a_src[tid]; sDst[tid] = a_dst[tid]; }
    }

#pragma unroll
    for (int i = 0; i < 16; i++) {
        int idx = tid + 256 * i;
        int r = idx >> 5, q = idx & 31;
        int grow = row0 + r;
        float4 v = make_float4(0.f, 0.f, 0.f, 0.f);
        if (grow < NN) {
            v = ((const float4*)A)[grow * 32 + q];
            if (NORM) {
                int g = batch[grow];
                float4 a4 = ((const float4*)g_nA)[g * 32 + q];
                float4 b4 = ((const float4*)g_nB)[g * 32 + q];
                v.x = fmaf(v.x, a4.x, b4.x);
                v.y = fmaf(v.y, a4.y, b4.y);
                v.z = fmaf(v.z, a4.z, b4.z);
                v.w = fmaf(v.w, a4.w, b4.w);
            }
        }
        *(float4*)&aT[r * 132 + q * 4] = v;
    }
    __syncthreads();

    float d[2][8][4];
#pragma unroll
    for (int mt = 0; mt < 2; mt++)
#pragma unroll
        for (int nt = 0; nt < 8; nt++)
#pragma unroll
            for (int f = 0; f < 4; f++) d[mt][nt][f] = 0.f;

    const uint4* wf = g_wfrag + WSEL * 8192;

#pragma unroll 4
    for (int ktG = 0; ktG < 16; ktG++) {
        uint4 bb[8];
#pragma unroll
        for (int nt = 0; nt < 8; nt++)
            bb[nt] = wf[(((wn * 8 + nt) << 4) + ktG) * 32 + lane];
        uint32_t aH[2][4], aL[2][4];
#pragma unroll
        for (int mt = 0; mt < 2; mt++) {
            int rb = wm * 32 + mt * 16 + gid;
            int c = ktG * 8 + tig;
            float v0 = aT[rb * 132 + c];
            float v1 = aT[(rb + 8) * 132 + c];
            float v2 = aT[rb * 132 + c + 4];
            float v3 = aT[(rb + 8) * 132 + c + 4];
            aH[mt][0] = tf32rn(v0); aL[mt][0] = tf32rn(v0 - __uint_as_float(aH[mt][0]));
            aH[mt][1] = tf32rn(v1); aL[mt][1] = tf32rn(v1 - __uint_as_float(aH[mt][1]));
            aH[mt][2] = tf32rn(v2); aL[mt][2] = tf32rn(v2 - __uint_as_float(aH[mt][2]));
            aH[mt][3] = tf32rn(v3); aL[mt][3] = tf32rn(v3 - __uint_as_float(aH[mt][3]));
        }
#pragma unroll
        for (int nt = 0; nt < 8; nt++)
#pragma unroll
            for (int mt = 0; mt < 2; mt++) {
                mma8(d[mt][nt], aH[mt][0], aH[mt][1], aH[mt][2], aH[mt][3], bb[nt].x, bb[nt].y);
                mma8(d[mt][nt], aH[mt][0], aH[mt][1], aH[mt][2], aH[mt][3], bb[nt].z, bb[nt].w);
                mma8(d[mt][nt], aL[mt][0], aL[mt][1], aL[mt][2], aL[mt][3], bb[nt].x, bb[nt].y);
            }
    }

    // epilogue: store (fp32 encoder / fp16 layers) + fused scores + fused max
    float sc[2][2][2][2];
    if (SCORES) {
#pragma unroll
        for (int a = 0; a < 2; a++)
#pragma unroll
            for (int b = 0; b < 2; b++)
#pragma unroll
                for (int c = 0; c < 2; c++) {
                    sc[a][b][c][0] = 0.f; sc[a][b][c][1] = 0.f;
                }
    }
#pragma unroll
    for (int mt = 0; mt < 2; mt++) {
        int r0 = row0 + wm * 32 + mt * 16 + gid;
#pragma unroll
        for (int nt = 0; nt < 8; nt++) {
            int c0 = wn * 64 + nt * 8 + 2 * tig;
            float v0 = d[mt][nt][0], v1 = d[mt][nt][1];
            float v2 = d[mt][nt][2], v3 = d[mt][nt][3];
            if (SCORES) {
                int hh = nt >> 2;
                float s0 = sSrc[c0], s1 = sSrc[c0 + 1];
                float t0 = sDst[c0], t1 = sDst[c0 + 1];
                sc[mt][0][hh][0] += v0 * s0 + v1 * s1;
                sc[mt][0][hh][1] += v0 * t0 + v1 * t1;
                sc[mt][1][hh][0] += v2 * s0 + v3 * s1;
                sc[mt][1][hh][1] += v2 * t0 + v3 * t1;
            }
            if (BIAS) {
                float b0 = sBia[c0], b1 = sBia[c0 + 1];
                v0 += b0; v1 += b1; v2 += b0; v3 += b1;
            }
            if (r0 < NN) {
                if (DSEL == 0) *(float2*)&g_bufX[r0 * CATC + c0] = make_float2(v0, v1);
                else           g_bufH16[r0 * 64 + (c0 >> 1)] = __floats2half2_rn(v0, v1);
            }
            if (r0 + 8 < NN) {
                if (DSEL == 0) *(float2*)&g_bufX[(r0 + 8) * CATC + c0] = make_float2(v2, v3);
                else           g_bufH16[(r0 + 8) * 64 + (c0 >> 1)] = __floats2half2_rn(v2, v3);
            }
        }
    }
    if (SCORES) {
#pragma unroll
        for (int a = 0; a < 2; a++)
#pragma unroll
            for (int b = 0; b < 2; b++)
#pragma unroll
                for (int c = 0; c < 2; c++)
#pragma unroll
                    for (int s = 0; s < 2; s++) {
                        float v = sc[a][b][c][s];
                        v += __shfl_xor_sync(0xffffffffu, v, 1);
                        v += __shfl_xor_sync(0xffffffffu, v, 2);
                        sc[a][b][c][s] = v;
                    }
        if (tig == 0) {
#pragma unroll
            for (int mt = 0; mt < 2; mt++)
#pragma unroll
                for (int rh = 0; rh < 2; rh++) {
                    int r = row0 + wm * 32 + mt * 16 + gid + rh * 8;
                    if (r < NN) {
#pragma unroll
                        for (int hh = 0; hh < 2; hh++) {
                            int head = wn * 2 + hh;
                            g_ssrc[r * 4 + head] = sc[mt][rh][hh][0];
                            g_sdst[r * 4 + head] = sc[mt][rh][hh][1];
                        }
                    }
                }
        }
        // fused per-head global max (padded rows add score 0 — softmax
        // shift-invariance makes any finite upper bound valid)
#pragma unroll
        for (int hh = 0; hh < 2; hh++) {
            float ms = fmaxf(fmaxf(sc[0][0][hh][0], sc[0][1][hh][0]),
                             fmaxf(sc[1][0][hh][0], sc[1][1][hh][0]));
            float md = fmaxf(fmaxf(sc[0][0][hh][1], sc[0][1][hh][1]),
                             fmaxf(sc[1][0][hh][1], sc[1][1][hh][1]));
#pragma unroll
            for (int off = 4; off <= 16; off <<= 1) {
                ms = fmaxf(ms, __shfl_xor_sync(0xffffffffu, ms, off));
                md = fmaxf(md, __shfl_xor_sync(0xffffffffu, md, off));
            }
            if (lane == 0) {
                atomicMaxF(&g_maxs[wn * 2 + hh], ms);
                atomicMaxF(&g_maxd[wn * 2 + hh], md);
            }
        }
    }
}

// ---------------- pre: zero counts + preset g_start + max init ----------------
__global__ void k_pre() {
    int i = blockIdx.x * blockDim.x + threadIdx.x;
    if (i < NN) g_cnt[i] = 0;
    if (i <= NG) g_start[i] = NN;
    if (i < NHEAD) {
        g_maxs[i] = __int_as_float(0xff800000u);
        g_maxd[i] = __int_as_float(0xff800000u);
    }
}
__global__ void k_start_fill(const int* __restrict__ batch) {
    int i = blockIdx.x * blockDim.x + threadIdx.x;
    if (i >= NN) return;
    int b = batch[i];
    int bp = (i == 0) ? -1 : batch[i - 1];
    for (int g = bp + 1; g <= b; ++g) g_start[g] = i;
}
__global__ void k_scan1() {
    __shared__ int wsum[8];
    int b = blockIdx.x, t = threadIdx.x;
    int idx0 = b * 1024 + t * 4;
    int v[4];
#pragma unroll
    for (int k = 0; k < 4; k++) v[k] = (idx0 + k < NN) ? g_cnt[idx0 + k] : 0;
    int s = v[0] + v[1] + v[2] + v[3];
    int lane = t & 31, wid = t >> 5;
    int incl = s;
#pragma unroll
    for (int off = 1; off <= 16; off <<= 1) {
        int nv = __shfl_up_sync(0xffffffffu, incl, off);
        if (lane >= off) incl += nv;
    }
    if (lane == 31) wsum[wid] = incl;
    __syncthreads();
    if (t == 0) {
        int r = 0;
#pragma unroll
        for (int w = 0; w < 8; w++) { int x = wsum[w]; wsum[w] = r; r += x; }
    }
    __syncthreads();
    int excl = incl - s + wsum[wid];
    int run = excl;
#pragma unroll
    for (int k = 0; k < 4; k++) {
        if (idx0 + k < NN) g_off[idx0 + k] = run;
        run += v[k];
    }
    if (t == 255) g_bsum[b] = excl + s;
}
__global__ void k_scan2() {
    int r = 0;
    for (int b = 0; b < SCAN_B; b++) { g_boff[b] = r; r += g_bsum[b]; }
    g_off[NN] = r;
}
__global__ void k_scan3() {
    int i = blockIdx.x * blockDim.x + threadIdx.x;
    if (i >= NN) return;
    int o = g_off[i] + g_boff[i >> 10];
    g_off[i] = o;
    g_cursor[i] = o;
}

// ---------------- fused GAT aggregate (warp per dst, fp16 gather) ----------------
__global__ void k_gat(const float* __restrict__ bias) {
    int n = (blockIdx.x * blockDim.x + threadIdx.x) >> 5;
    if (n >= NN) return;
    int lane = threadIdx.x & 31;
    int head = lane >> 3;

    float shift = lrelu(g_maxs[head] + g_maxd[head]);
    float sd = g_sdst[n * 4 + head];

    // self-loop (fp16 h)
    float p = __expf(lrelu(g_ssrc[n * 4 + head] + sd) - shift);
    uint2 hs = ((const uint2*)g_bufH16)[n * 32 + lane];
    float2 s01 = __half22float2(*(__half2*)&hs.x);
    float2 s23 = __half22float2(*(__half2*)&hs.y);
    float ax = s01.x * p, ay = s01.y * p, az = s23.x * p, aw = s23.y * p;
    float den = p;

    int o0 = g_off[n], o1 = g_off[n + 1];
    for (int base = o0; base < o1; base += 32) {
        int id = 0;
        if (base + lane < o1) id = g_csr[base + lane];
        int cnt = min(32, o1 - base);
#pragma unroll 4
        for (int j = 0; j < cnt; j++) {
            int src = __shfl_sync(0xffffffffu, id, j);
            float ss = g_ssrc[src * 4 + head];
            float pe = __expf(lrelu(ss + sd) - shift);
            uint2 hraw = ((const uint2*)g_bufH16)[src * 32 + lane];
            float2 f01 = __half22float2(*(__half2*)&hraw.x);
            float2 f23 = __half22float2(*(__half2*)&hraw.y);
            ax += f01.x * pe; ay += f01.y * pe;
            az += f23.x * pe; aw += f23.y * pe;
            den += pe;
        }
    }
    float inv = 1.f / den;
    float4 b = ((const float4*)bias)[lane];
    float4 o;
    o.x = eluf(ax * inv + b.x);
    o.y = eluf(ay * inv + b.y);
    o.z = eluf(az * inv + b.z);
    o.w = eluf(aw * inv + b.w);
    ((float4*)g_bufX)[n * 32 + lane] = o;
}

// -------- GraphNorm stats -> affine A',B'  (+optional per-head max reset) -------
template <bool RESET_MAX>
__global__ void k_norm_stats(const float* __restrict__ nw,
                             const float* __restrict__ nb,
                             const float* __restrict__ nms) {
    __shared__ float sh[256], sh2[256];
    int g = blockIdx.x, q = blockIdx.y;
    // fold the k_shift_init launch into layer-1's stats pass: reset maxima
    // for the NEXT layer (safe: norm_stats never reads g_maxs/g_maxd, and it
    // runs after this layer's k_gat consumed them).
    if (RESET_MAX && g == 0 && q == 0 && threadIdx.x < NHEAD) {
        g_maxs[threadIdx.x] = __int_as_float(0xff800000u);
        g_maxd[threadIdx.x] = __int_as_float(0xff800000u);
    }
    int tc = threadIdx.x & 31, tr = threadIdx.x >> 5;
    int c = q * 32 + tc;
    int s0 = g_start[g], s1 = g_start[g + 1];
    float s = 0.f, s2 = 0.f;
    for (int r = s0 + tr; r < s1; r += 8) {
        float v = g_bufX[r * CATC + c];
        s += v; s2 += v * v;
    }
    sh[threadIdx.x] = s; sh2[threadIdx.x] = s2;
    __syncthreads();
    for (int off = 128; off >= 32; off >>= 1) {
        if (threadIdx.x < off) {
            sh[threadIdx.x] += sh[threadIdx.x + off];
            sh2[threadIdx.x] += sh2[threadIdx.x + off];
        }
        __syncthreads();
    }
    if (threadIdx.x < 32) {
        int cnt = s1 - s0;
        float A = 0.f, B = nb[c];
        if (cnt > 0) {
            float fc = (float)cnt;
            float mean = sh[tc] / fc;
            float ms = nms[c];
            float var = sh2[tc] / fc - (2.f * ms - ms * ms) * mean * mean;
            float inv = rsqrtf(var + EPSN);
            A = nw[c] * inv;
            B = nb[c] - A * ms * mean;
        }
        g_nA[g * CATC + c] = A;
        g_nB[g * CATC + c] = B;
    }
}

// ---------------- global max pool (+fused norm2 affine) ----------------
__global__ void k_pool() {
    __shared__ float sh[256];
    int g = blockIdx.x, q = blockIdx.y;
    int tc = threadIdx.x & 31, tr = threadIdx.x >> 5;
    int c = q * 32 + tc;
    int s0 = g_start[g], s1 = g_start[g + 1];
    float a = g_nA[g * CATC + c], b = g_nB[g * CATC + c];
    float m = __int_as_float(0xff800000u);
    for (int r = s0 + tr; r < s1; r += 8)
        m = fmaxf(m, fmaf(g_bufX[r * CATC + c], a, b));
    sh[threadIdx.x] = m;
    __syncthreads();
    for (int off = 128; off >= 32; off >>= 1) {
        if (threadIdx.x < off) sh[threadIdx.x] = fmaxf(sh[threadIdx.x], sh[threadIdx.x + off]);
        __syncthreads();
    }
    if (threadIdx.x < 32) g_pool[g * CATC + c] = sh[tc];
}

// ---------------- final fc ----------------
__global__ void k_fc(const float* __restrict__ fw, const float* __restrict__ fb,
                     float* __restrict__ out) {
    int g = blockIdx.x, o = threadIdx.x;
    float acc = fb[o];
#pragma unroll
    for (int c = 0; c < CATC; c += 4) {
        float4 p  = *(const float4*)&g_pool[g * CATC + c];
        float4 wv = *(const float4*)&fw[o * CATC + c];
        acc += p.x * wv.x + p.y * wv.y + p.z * wv.z + p.w * wv.w;
    }
    out[g * OUTD + o] = acc;
}

// ---------------- launch ----------------
extern "C" void kernel_launch(void* const* d_in, const int* in_sizes, int n_in,
                              void* d_out, int out_size) {
    const float* x     = (const float*)d_in[0];
    const int*   ei    = (const int*)d_in[1];
    const int*   batch = (const int*)d_in[2];
    const float* enc_w = (const float*)d_in[3];
    const float* enc_b = (const float*)d_in[4];
    const float* w1    = (const float*)d_in[5];
    const float* as1   = (const float*)d_in[6];
    const float* ad1   = (const float*)d_in[7];
    const float* b1    = (const float*)d_in[8];
    const float* n1w   = (const float*)d_in[9];
    const float* n1b   = (const float*)d_in[10];
    const float* n1ms  = (const float*)d_in[11];
    const float* w2    = (const float*)d_in[12];
    const float* as2   = (const float*)d_in[13];
    const float* ad2   = (const float*)d_in[14];
    const float* b2    = (const float*)d_in[15];
    const float* n2w   = (const float*)d_in[16];
    const float* n2b   = (const float*)d_in[17];
    const float* n2ms  = (const float*)d_in[18];
    const float* fw    = (const float*)d_in[19];
    const float* fb    = (const float*)d_in[20];
    float* out = (float*)d_out;

    cudaFuncSetAttribute(k_tgemm<0, 0, 0, true, false, false, 1>,
                         cudaFuncAttributeMaxDynamicSharedMemorySize, TG_SMEM);
    cudaFuncSetAttribute(k_tgemm<1, 1, 1, false, true, false, 2>,
                         cudaFuncAttributeMaxDynamicSharedMemorySize, TG_SMEM);
    cudaFuncSetAttribute(k_tgemm<1, 1, 2, false, true, true, 0>,
                         cudaFuncAttributeMaxDynamicSharedMemorySize, TG_SMEM);

    const int gatBlocks = (NN * 32 + 255) / 256;

    // prep (counts zeroed, g_start preset, maxima init for layer 1, W fragments)
    k_pre<<<(NN + 255) / 256, 256>>>();
    k_start_fill<<<(NN + 255) / 256, 256>>>(batch);
    k_wconv3<<<96, 256>>>(enc_w, w1, w2);

    // encoder GEMM + degree-count tail blocks (overlapped)
    k_tgemm<0, 0, 0, true, false, false, 1><<<GEMMB + EDGE4B, 256, TG_SMEM>>>(
        x, enc_b, nullptr, nullptr, nullptr, ei);

    // prefix scan (needs degrees)
    k_scan1<<<SCAN_B, 256>>>();
    k_scan2<<<1, 1>>>();
    k_scan3<<<(NN + 255) / 256, 256>>>();

    // ---- layer 1 GEMM (scores + fused max) + CSR-fill tail blocks ----
    k_tgemm<1, 1, 1, false, true, false, 2><<<GEMMB + EDGE4B, 256, TG_SMEM>>>(
        nullptr, nullptr, as1, ad1, nullptr, ei);
    k_gat<<<gatBlocks, 256>>>(b1);
    // stats for norm1 + reset per-head maxima for layer 2 (folded k_shift_init)
    k_norm_stats<true><<<dim3(NG, 4), 256>>>(n1w, n1b, n1ms);

    // ---- layer 2 (A-staging applies norm1 affine) ----
    k_tgemm<1, 1, 2, false, true, true, 0><<<GEMMB, 256, TG_SMEM>>>(
        nullptr, nullptr, as2, ad2, batch, nullptr);
    k_gat<<<gatBlocks, 256>>>(b2);
    k_norm_stats<false><<<dim3(NG, 4), 256>>>(n2w, n2b, n2ms);

    // ---- pool (applies norm2 affine) + fc ----
    k_pool<<<dim3(NG, 4), 256>>>();
    k_fc<<<NG, OUTD>>>(fw, fb, out);
}

// round 16
// speedup vs baseline: 1.3171x; 1.0106x over previous
#include <cuda_runtime.h>
#include <cuda_fp16.h>
#include <math.h>
#include <stdint.h>

#define NN    100000
#define NE    1600000
#define NG    64
#define CATC  128
#define NHEAD 4
#define OUTD  64
#define EPSN  1e-5f
#define SLOPE 0.2f
#define SCAN_B ((NN + 1023) / 1024)   // 98
#define GEMMB ((NN + 127) / 128)      // 782
#define EDGE4B ((NE / 4 + 255) / 256) // 1563

// ---------------- scratch (device globals) ----------------
__device__ float   g_bufX[NN * CATC];
__device__ __half2 g_bufH16[NN * 64];
__device__ float   g_ssrc[NN * NHEAD];
__device__ float   g_sdst[NN * NHEAD];
__device__ float   g_maxs[NHEAD];
__device__ float   g_maxd[NHEAD];
__device__ float   g_nA[NG * CATC];
__device__ float   g_nB[NG * CATC];
__device__ float   g_pool[NG * CATC];
__device__ int     g_start[NG + 2];
__device__ int     g_cnt[NN];
__device__ int     g_off[NN + 1];
__device__ int     g_cursor[NN];
__device__ int     g_bsum[SCAN_B];
__device__ int     g_csr[NE];
__device__ uint4   g_wfrag[3 * 16 * 16 * 32];  // [layer][ntG][ktG][lane]

__device__ __forceinline__ float lrelu(float x) { return x > 0.f ? x : SLOPE * x; }
__device__ __forceinline__ float eluf(float x)  { return x > 0.f ? x : __expf(x) - 1.f; }

__device__ __forceinline__ void atomicMaxF(float* a, float v) {
    if (v >= 0.f) atomicMax((int*)a, __float_as_int(v));
    else          atomicMin((unsigned int*)a, __float_as_uint(v));
}

__device__ __forceinline__ uint32_t tf32rn(float x) {
    uint32_t r;
    asm("cvt.rna.tf32.f32 %0, %1;" : "=r"(r) : "f"(x));
    return r;
}
__device__ __forceinline__ void mma8(float* d, uint32_t a0, uint32_t a1,
                                     uint32_t a2, uint32_t a3,
                                     uint32_t b0, uint32_t b1) {
    asm volatile(
        "mma.sync.aligned.m16n8k8.row.col.f32.tf32.tf32.f32 "
        "{%0,%1,%2,%3}, {%4,%5,%6,%7}, {%8,%9}, {%0,%1,%2,%3};"
        : "+f"(d[0]), "+f"(d[1]), "+f"(d[2]), "+f"(d[3])
        : "r"(a0), "r"(a1), "r"(a2), "r"(a3), "r"(b0), "r"(b1));
}

// -------- prep (merged): zero counts, preset g_start, max init, W fragments,
//          graph segment offsets. All index-disjoint; one launch. ----------------
__global__ void k_prep(const int* __restrict__ batch,
                       const float* __restrict__ w0,
                       const float* __restrict__ w1,
                       const float* __restrict__ w2) {
    int i = blockIdx.x * blockDim.x + threadIdx.x;
    if (i < NN) {
        g_cnt[i] = 0;
        int b = batch[i];
        int bp = (i == 0) ? -1 : batch[i - 1];
        for (int g = bp + 1; g <= b; ++g) g_start[g] = i;
        if (batch[NN - 1] < NG && i == 0) {
            for (int g = batch[NN - 1] + 1; g <= NG; ++g) g_start[g] = NN;
        }
    }
    if (i == 0) g_start[NG] = NN;           // safety (overwritten above if needed)
    if (i < NHEAD) {
        g_maxs[i] = __int_as_float(0xff800000u);
        g_maxd[i] = __int_as_float(0xff800000u);
    }
    if (i < 3 * 8192) {
        int l = i >> 13, s = i & 8191;
        const float* W = (l == 0) ? w0 : (l == 1) ? w1 : w2;
        int lane = s & 31, ktG = (s >> 5) & 15, ntG = s >> 9;
        int n = ntG * 8 + (lane >> 2);
        int k0 = ktG * 8 + (lane & 3);
        float v0 = W[n * CATC + k0];
        float v1 = W[n * CATC + k0 + 4];
        uint4 f;
        f.x = tf32rn(v0);
        f.y = tf32rn(v1);
        f.z = tf32rn(v0 - __uint_as_float(f.x));
        f.w = tf32rn(v1 - __uint_as_float(f.y));
        g_wfrag[i] = f;
    }
}

// ------ TF32 tensor GEMM 3xTF32 (+bias)(+scores+max)(+norm)(+CSR tails) ---------
// TAIL: 0 = none, 1 = degree-count tail, 2 = csr-fill tail
#define TG_SMEM ((128 * 132 + 384) * 4)

template <int ASEL, int DSEL, int WSEL, bool BIAS, bool SCORES, bool NORM, int TAIL>
__global__ void __launch_bounds__(256, 2)
k_tgemm(const float* __restrict__ Aext,
        const float* __restrict__ bias,
        const float* __restrict__ a_src,
        const float* __restrict__ a_dst,
        const int* __restrict__ batch,
        const int* __restrict__ ei) {
    extern __shared__ float sm[];
    int tid = threadIdx.x;

    // -------- CSR tail blocks (atomic-latency work hidden under GEMM) --------
    if (TAIL != 0) {
        int tb = (int)blockIdx.x - GEMMB;
        if (tb >= 0) {
            int t = tb * 256 + tid;
            if (t < NE / 4) {
                if (TAIL == 1) {
                    int4 d4 = ((const int4*)(ei + NE))[t];
                    atomicAdd(&g_cnt[d4.x], 1);
                    atomicAdd(&g_cnt[d4.y], 1);
                    atomicAdd(&g_cnt[d4.z], 1);
                    atomicAdd(&g_cnt[d4.w], 1);
                } else {
                    int4 s4 = ((const int4*)ei)[t];
                    int4 d4 = ((const int4*)(ei + NE))[t];
                    g_csr[atomicAdd(&g_cursor[d4.x], 1)] = s4.x;
                    g_csr[atomicAdd(&g_cursor[d4.y], 1)] = s4.y;
                    g_csr[atomicAdd(&g_cursor[d4.z], 1)] = s4.z;
                    g_csr[atomicAdd(&g_cursor[d4.w], 1)] = s4.w;
                }
            }
            return;
        }
    }

    float* aT   = sm;                  // [128][132]
    float* sBia = sm + 128 * 132;
    float* sSrc = sBia + 128;
    float* sDst = sSrc + 128;

    const float* A = (ASEL == 0) ? Aext : g_bufX;

    int wid = tid >> 5, lane = tid & 31;
    int wm = wid >> 1, wn = wid & 1, gid = lane >> 2, tig = lane & 3;
    int row0 = blockIdx.x * 128;

    if (tid < 128) {
        if (BIAS) sBia[tid] = bias[tid];
        if (SCORES) { sSrc[tid] = a_src[tid]; sDst[tid] = a_dst[tid]; }
    }

#pragma unroll
    for (int i = 0; i < 16; i++) {
        int idx = tid + 256 * i;
        int r = idx >> 5, q = idx & 31;
        int grow = row0 + r;
        float4 v = make_float4(0.f, 0.f, 0.f, 0.f);
        if (grow < NN) {
            v = ((const float4*)A)[grow * 32 + q];
            if (NORM) {
                int g = batch[grow];
                float4 a4 = ((const float4*)g_nA)[g * 32 + q];
                float4 b4 = ((const float4*)g_nB)[g * 32 + q];
                v.x = fmaf(v.x, a4.x, b4.x);
                v.y = fmaf(v.y, a4.y, b4.y);
                v.z = fmaf(v.z, a4.z, b4.z);
                v.w = fmaf(v.w, a4.w, b4.w);
            }
        }
        *(float4*)&aT[r * 132 + q * 4] = v;
    }
    __syncthreads();

    float d[2][8][4];
#pragma unroll
    for (int mt = 0; mt < 2; mt++)
#pragma unroll
        for (int nt = 0; nt < 8; nt++)
#pragma unroll
            for (int f = 0; f < 4; f++) d[mt][nt][f] = 0.f;

    const uint4* wf = g_wfrag + WSEL * 8192;

#pragma unroll 4
    for (int ktG = 0; ktG < 16; ktG++) {
        uint4 bb[8];
#pragma unroll
        for (int nt = 0; nt < 8; nt++)
            bb[nt] = wf[(((wn * 8 + nt) << 4) + ktG) * 32 + lane];
        uint32_t aH[2][4], aL[2][4];
#pragma unroll
        for (int mt = 0; mt < 2; mt++) {
            int rb = wm * 32 + mt * 16 + gid;
            int c = ktG * 8 + tig;
            float v0 = aT[rb * 132 + c];
            float v1 = aT[(rb + 8) * 132 + c];
            float v2 = aT[rb * 132 + c + 4];
            float v3 = aT[(rb + 8) * 132 + c + 4];
            aH[mt][0] = tf32rn(v0); aL[mt][0] = tf32rn(v0 - __uint_as_float(aH[mt][0]));
            aH[mt][1] = tf32rn(v1); aL[mt][1] = tf32rn(v1 - __uint_as_float(aH[mt][1]));
            aH[mt][2] = tf32rn(v2); aL[mt][2] = tf32rn(v2 - __uint_as_float(aH[mt][2]));
            aH[mt][3] = tf32rn(v3); aL[mt][3] = tf32rn(v3 - __uint_as_float(aH[mt][3]));
        }
#pragma unroll
        for (int nt = 0; nt < 8; nt++)
#pragma unroll
            for (int mt = 0; mt < 2; mt++) {
                mma8(d[mt][nt], aH[mt][0], aH[mt][1], aH[mt][2], aH[mt][3], bb[nt].x, bb[nt].y);
                mma8(d[mt][nt], aH[mt][0], aH[mt][1], aH[mt][2], aH[mt][3], bb[nt].z, bb[nt].w);
                mma8(d[mt][nt], aL[mt][0], aL[mt][1], aL[mt][2], aL[mt][3], bb[nt].x, bb[nt].y);
            }
    }

    // epilogue: store (fp32 encoder / fp16 layers) + fused scores + fused max
    float sc[2][2][2][2];
    if (SCORES) {
#pragma unroll
        for (int a = 0; a < 2; a++)
#pragma unroll
            for (int b = 0; b < 2; b++)
#pragma unroll
                for (int c = 0; c < 2; c++) {
                    sc[a][b][c][0] = 0.f; sc[a][b][c][1] = 0.f;
                }
    }
#pragma unroll
    for (int mt = 0; mt < 2; mt++) {
        int r0 = row0 + wm * 32 + mt * 16 + gid;
#pragma unroll
        for (int nt = 0; nt < 8; nt++) {
            int c0 = wn * 64 + nt * 8 + 2 * tig;
            float v0 = d[mt][nt][0], v1 = d[mt][nt][1];
            float v2 = d[mt][nt][2], v3 = d[mt][nt][3];
            if (SCORES) {
                int hh = nt >> 2;
                float s0 = sSrc[c0], s1 = sSrc[c0 + 1];
                float t0 = sDst[c0], t1 = sDst[c0 + 1];
                sc[mt][0][hh][0] += v0 * s0 + v1 * s1;
                sc[mt][0][hh][1] += v0 * t0 + v1 * t1;
                sc[mt][1][hh][0] += v2 * s0 + v3 * s1;
                sc[mt][1][hh][1] += v2 * t0 + v3 * t1;
            }
            if (BIAS) {
                float b0 = sBia[c0], b1 = sBia[c0 + 1];
                v0 += b0; v1 += b1; v2 += b0; v3 += b1;
            }
            if (r0 < NN) {
                if (DSEL == 0) *(float2*)&g_bufX[r0 * CATC + c0] = make_float2(v0, v1);
                else           g_bufH16[r0 * 64 + (c0 >> 1)] = __floats2half2_rn(v0, v1);
            }
            if (r0 + 8 < NN) {
                if (DSEL == 0) *(float2*)&g_bufX[(r0 + 8) * CATC + c0] = make_float2(v2, v3);
                else           g_bufH16[(r0 + 8) * 64 + (c0 >> 1)] = __floats2half2_rn(v2, v3);
            }
        }
    }
    if (SCORES) {
#pragma unroll
        for (int a = 0; a < 2; a++)
#pragma unroll
            for (int b = 0; b < 2; b++)
#pragma unroll
                for (int c = 0; c < 2; c++)
#pragma unroll
                    for (int s = 0; s < 2; s++) {
                        float v = sc[a][b][c][s];
                        v += __shfl_xor_sync(0xffffffffu, v, 1);
                        v += __shfl_xor_sync(0xffffffffu, v, 2);
                        sc[a][b][c][s] = v;
                    }
        if (tig == 0) {
#pragma unroll
            for (int mt = 0; mt < 2; mt++)
#pragma unroll
                for (int rh = 0; rh < 2; rh++) {
                    int r = row0 + wm * 32 + mt * 16 + gid + rh * 8;
                    if (r < NN) {
#pragma unroll
                        for (int hh = 0; hh < 2; hh++) {
                            int head = wn * 2 + hh;
                            g_ssrc[r * 4 + head] = sc[mt][rh][hh][0];
                            g_sdst[r * 4 + head] = sc[mt][rh][hh][1];
                        }
                    }
                }
        }
        // fused per-head global max (padded rows add score 0 — softmax
        // shift-invariance makes any finite upper bound valid)
#pragma unroll
        for (int hh = 0; hh < 2; hh++) {
            float ms = fmaxf(fmaxf(sc[0][0][hh][0], sc[0][1][hh][0]),
                             fmaxf(sc[1][0][hh][0], sc[1][1][hh][0]));
            float md = fmaxf(fmaxf(sc[0][0][hh][1], sc[0][1][hh][1]),
                             fmaxf(sc[1][0][hh][1], sc[1][1][hh][1]));
#pragma unroll
            for (int off = 4; off <= 16; off <<= 1) {
                ms = fmaxf(ms, __shfl_xor_sync(0xffffffffu, ms, off));
                md = fmaxf(md, __shfl_xor_sync(0xffffffffu, md, off));
            }
            if (lane == 0) {
                atomicMaxF(&g_maxs[wn * 2 + hh], ms);
                atomicMaxF(&g_maxd[wn * 2 + hh], md);
            }
        }
    }
}

// ---------------- scan stage 1: per-1024-block exclusive scan + block sums ------
__global__ void k_scan1() {
    __shared__ int wsum[8];
    int b = blockIdx.x, t = threadIdx.x;
    int idx0 = b * 1024 + t * 4;
    int v[4];
#pragma unroll
    for (int k = 0; k < 4; k++) v[k] = (idx0 + k < NN) ? g_cnt[idx0 + k] : 0;
    int s = v[0] + v[1] + v[2] + v[3];
    int lane = t & 31, wid = t >> 5;
    int incl = s;
#pragma unroll
    for (int off = 1; off <= 16; off <<= 1) {
        int nv = __shfl_up_sync(0xffffffffu, incl, off);
        if (lane >= off) incl += nv;
    }
    if (lane == 31) wsum[wid] = incl;
    __syncthreads();
    if (t == 0) {
        int r = 0;
#pragma unroll
        for (int w = 0; w < 8; w++) { int x = wsum[w]; wsum[w] = r; r += x; }
    }
    __syncthreads();
    int excl = incl - s + wsum[wid];
    int run = excl;
#pragma unroll
    for (int k = 0; k < 4; k++) {
        if (idx0 + k < NN) g_off[idx0 + k] = run;
        run += v[k];
    }
    if (t == 255) g_bsum[b] = excl + s;
}

// ---------------- scan stage 2+3 merged: add block prefix, set cursors ----------
__global__ void k_scan23() {
    __shared__ int sOff;
    int i = blockIdx.x * blockDim.x + threadIdx.x;
    // each block spans indices within ONE 1024-group (256 | 1024)
    if (threadIdx.x == 0) {
        int grp = (blockIdx.x * blockDim.x) >> 10;
        int r = 0;
        for (int b = 0; b < grp; b++) r += g_bsum[b];
        sOff = r;
    }
    __syncthreads();
    if (i < NN) {
        int o = g_off[i] + sOff;
        g_off[i] = o;
        g_cursor[i] = o;
    }
    if (i == 0) {
        int r = 0;
        for (int b = 0; b < SCAN_B; b++) r += g_bsum[b];
        g_off[NN] = r;
    }
}

// ---------------- fused GAT aggregate (warp per dst, fp16 gather) ----------------
__global__ void k_gat(const float* __restrict__ bias) {
    int n = (blockIdx.x * blockDim.x + threadIdx.x) >> 5;
    if (n >= NN) return;
    int lane = threadIdx.x & 31;
    int head = lane >> 3;

    float shift = lrelu(g_maxs[head] + g_maxd[head]);
    float sd = g_sdst[n * 4 + head];

    // self-loop (fp16 h)
    float p = __expf(lrelu(g_ssrc[n * 4 + head] + sd) - shift);
    uint2 hs = ((const uint2*)g_bufH16)[n * 32 + lane];
    float2 s01 = __half22float2(*(__half2*)&hs.x);
    float2 s23 = __half22float2(*(__half2*)&hs.y);
    float ax = s01.x * p, ay = s01.y * p, az = s23.x * p, aw = s23.y * p;
    float den = p;

    int o0 = g_off[n], o1 = g_off[n + 1];
    for (int base = o0; base < o1; base += 32) {
        int id = 0;
        if (base + lane < o1) id = g_csr[base + lane];
        int cnt = min(32, o1 - base);
#pragma unroll 4
        for (int j = 0; j < cnt; j++) {
            int src = __shfl_sync(0xffffffffu, id, j);
            float ss = g_ssrc[src * 4 + head];
            float pe = __expf(lrelu(ss + sd) - shift);
            uint2 hraw = ((const uint2*)g_bufH16)[src * 32 + lane];
            float2 f01 = __half22float2(*(__half2*)&hraw.x);
            float2 f23 = __half22float2(*(__half2*)&hraw.y);
            ax += f01.x * pe; ay += f01.y * pe;
            az += f23.x * pe; aw += f23.y * pe;
            den += pe;
        }
    }
    float inv = 1.f / den;
    float4 b = ((const float4*)bias)[lane];
    float4 o;
    o.x = eluf(ax * inv + b.x);
    o.y = eluf(ay * inv + b.y);
    o.z = eluf(az * inv + b.z);
    o.w = eluf(aw * inv + b.w);
    ((float4*)g_bufX)[n * 32 + lane] = o;
}

// -------- GraphNorm stats -> affine A',B'  (+optional per-head max reset) -------
template <bool RESET_MAX>
__global__ void k_norm_stats(const float* __restrict__ nw,
                             const float* __restrict__ nb,
                             const float* __restrict__ nms) {
    __shared__ float sh[256], sh2[256];
    int g = blockIdx.x, q = blockIdx.y;
    if (RESET_MAX && g == 0 && q == 0 && threadIdx.x < NHEAD) {
        g_maxs[threadIdx.x] = __int_as_float(0xff800000u);
        g_maxd[threadIdx.x] = __int_as_float(0xff800000u);
    }
    int tc = threadIdx.x & 31, tr = threadIdx.x >> 5;
    int c = q * 32 + tc;
    int s0 = g_start[g], s1 = g_start[g + 1];
    float s = 0.f, s2 = 0.f;
    for (int r = s0 + tr; r < s1; r += 8) {
        float v = g_bufX[r * CATC + c];
        s += v; s2 += v * v;
    }
    sh[threadIdx.x] = s; sh2[threadIdx.x] = s2;
    __syncthreads();
    for (int off = 128; off >= 32; off >>= 1) {
        if (threadIdx.x < off) {
            sh[threadIdx.x] += sh[threadIdx.x + off];
            sh2[threadIdx.x] += sh2[threadIdx.x + off];
        }
        __syncthreads();
    }
    if (threadIdx.x < 32) {
        int cnt = s1 - s0;
        float A = 0.f, B = nb[c];
        if (cnt > 0) {
            float fc = (float)cnt;
            float mean = sh[tc] / fc;
            float ms = nms[c];
            float var = sh2[tc] / fc - (2.f * ms - ms * ms) * mean * mean;
            float inv = rsqrtf(var + EPSN);
            A = nw[c] * inv;
            B = nb[c] - A * ms * mean;
        }
        g_nA[g * CATC + c] = A;
        g_nB[g * CATC + c] = B;
    }
}

// ---------------- global max pool (+fused norm2 affine) ----------------
__global__ void k_pool() {
    __shared__ float sh[256];
    int g = blockIdx.x, q = blockIdx.y;
    int tc = threadIdx.x & 31, tr = threadIdx.x >> 5;
    int c = q * 32 + tc;
    int s0 = g_start[g], s1 = g_start[g + 1];
    float a = g_nA[g * CATC + c], b = g_nB[g * CATC + c];
    float m = __int_as_float(0xff800000u);
    for (int r = s0 + tr; r < s1; r += 8)
        m = fmaxf(m, fmaf(g_bufX[r * CATC + c], a, b));
    sh[threadIdx.x] = m;
    __syncthreads();
    for (int off = 128; off >= 32; off >>= 1) {
        if (threadIdx.x < off) sh[threadIdx.x] = fmaxf(sh[threadIdx.x], sh[threadIdx.x + off]);
        __syncthreads();
    }
    if (threadIdx.x < 32) g_pool[g * CATC + c] = sh[tc];
}

// ---------------- final fc ----------------
__global__ void k_fc(const float* __restrict__ fw, const float* __restrict__ fb,
                     float* __restrict__ out) {
    int g = blockIdx.x, o = threadIdx.x;
    float acc = fb[o];
#pragma unroll
    for (int c = 0; c < CATC; c += 4) {
        float4 p  = *(const float4*)&g_pool[g * CATC + c];
        float4 wv = *(const float4*)&fw[o * CATC + c];
        acc += p.x * wv.x + p.y * wv.y + p.z * wv.z + p.w * wv.w;
    }
    out[g * OUTD + o] = acc;
}

// ---------------- launch ----------------
extern "C" void kernel_launch(void* const* d_in, const int* in_sizes, int n_in,
                              void* d_out, int out_size) {
    const float* x     = (const float*)d_in[0];
    const int*   ei    = (const int*)d_in[1];
    const int*   batch = (const int*)d_in[2];
    const float* enc_w = (const float*)d_in[3];
    const float* enc_b = (const float*)d_in[4];
    const float* w1    = (const float*)d_in[5];
    const float* as1   = (const float*)d_in[6];
    const float* ad1   = (const float*)d_in[7];
    const float* b1    = (const float*)d_in[8];
    const float* n1w   = (const float*)d_in[9];
    const float* n1b   = (const float*)d_in[10];
    const float* n1ms  = (const float*)d_in[11];
    const float* w2    = (const float*)d_in[12];
    const float* as2   = (const float*)d_in[13];
    const float* ad2   = (const float*)d_in[14];
    const float* b2    = (const float*)d_in[15];
    const float* n2w   = (const float*)d_in[16];
    const float* n2b   = (const float*)d_in[17];
    const float* n2ms  = (const float*)d_in[18];
    const float* fw    = (const float*)d_in[19];
    const float* fb    = (const float*)d_in[20];
    float* out = (float*)d_out;

    cudaFuncSetAttribute(k_tgemm<0, 0, 0, true, false, false, 1>,
                         cudaFuncAttributeMaxDynamicSharedMemorySize, TG_SMEM);
    cudaFuncSetAttribute(k_tgemm<1, 1, 1, false, true, false, 2>,
                         cudaFuncAttributeMaxDynamicSharedMemorySize, TG_SMEM);
    cudaFuncSetAttribute(k_tgemm<1, 1, 2, false, true, true, 0>,
                         cudaFuncAttributeMaxDynamicSharedMemorySize, TG_SMEM);

    const int gatBlocks = (NN * 32 + 255) / 256;

    // prep (merged: counts, g_start, maxima, W fragments) — one launch
    k_prep<<<(NN + 255) / 256, 256>>>(batch, enc_w, w1, w2);

    // encoder GEMM + degree-count tail blocks (overlapped)
    k_tgemm<0, 0, 0, true, false, false, 1><<<GEMMB + EDGE4B, 256, TG_SMEM>>>(
        x, enc_b, nullptr, nullptr, nullptr, ei);

    // prefix scan (merged stages 2+3)
    k_scan1<<<SCAN_B, 256>>>();
    k_scan23<<<(NN + 255) / 256, 256>>>();

    // ---- layer 1 GEMM (scores + fused max) + CSR-fill tail blocks ----
    k_tgemm<1, 1, 1, false, true, false, 2><<<GEMMB + EDGE4B, 256, TG_SMEM>>>(
        nullptr, nullptr, as1, ad1, nullptr, ei);
    k_gat<<<gatBlocks, 256>>>(b1);
    // stats for norm1 + reset per-head maxima for layer 2 (folded k_shift_init)
    k_norm_stats<true><<<dim3(NG, 4), 256>>>(n1w, n1b, n1ms);

    // ---- layer 2 (A-staging applies norm1 affine) ----
    k_tgemm<1, 1, 2, false, true, true, 0><<<GEMMB, 256, TG_SMEM>>>(
        nullptr, nullptr, as2, ad2, batch, nullptr);
    k_gat<<<gatBlocks, 256>>>(b2);
    k_norm_stats<false><<<dim3(NG, 4), 256>>>(n2w, n2b, n2ms);

    // ---- pool (applies norm2 affine) + fc ----
    k_pool<<<dim3(NG, 4), 256>>>();
    k_fc<<<NG, OUTD>>>(fw, fb, out);
}

// round 17
// speedup vs baseline: 1.3185x; 1.0010x over previous
#include <cuda_runtime.h>
#include <cuda_fp16.h>
#include <math.h>
#include <stdint.h>

#define NN    100000
#define NE    1600000
#define NG    64
#define CATC  128
#define NHEAD 4
#define OUTD  64
#define EPSN  1e-5f
#define SLOPE 0.2f
#define SCAN_B ((NN + 1023) / 1024)   // 98
#define GEMMB ((NN + 127) / 128)      // 782
#define EDGE4B ((NE / 4 + 255) / 256) // 1563

// ---------------- scratch (device globals) ----------------
__device__ float   g_bufX[NN * CATC];
__device__ __half2 g_bufH16[NN * 64];
__device__ float   g_ssrc[NN * NHEAD];
__device__ float   g_sdst[NN * NHEAD];
__device__ float   g_maxs[NHEAD];
__device__ float   g_maxd[NHEAD];
__device__ float   g_nA[NG * CATC];
__device__ float   g_nB[NG * CATC];
__device__ float   g_pool[NG * CATC];
__device__ int     g_start[NG + 2];
__device__ int     g_cnt[NN];
__device__ int     g_off[NN + 1];
__device__ int     g_cursor[NN];
__device__ int     g_bsum[SCAN_B];
__device__ int     g_csr[NE];
__device__ uint4   g_wfrag[3 * 16 * 16 * 32];  // [layer][ntG][ktG][lane]

__device__ __forceinline__ float lrelu(float x) { return x > 0.f ? x : SLOPE * x; }
__device__ __forceinline__ float eluf(float x)  { return x > 0.f ? x : __expf(x) - 1.f; }

__device__ __forceinline__ void atomicMaxF(float* a, float v) {
    if (v >= 0.f) atomicMax((int*)a, __float_as_int(v));
    else          atomicMin((unsigned int*)a, __float_as_uint(v));
}

__device__ __forceinline__ uint32_t tf32rn(float x) {
    uint32_t r;
    asm("cvt.rna.tf32.f32 %0, %1;" : "=r"(r) : "f"(x));
    return r;
}
__device__ __forceinline__ void mma8(float* d, uint32_t a0, uint32_t a1,
                                     uint32_t a2, uint32_t a3,
                                     uint32_t b0, uint32_t b1) {
    asm volatile(
        "mma.sync.aligned.m16n8k8.row.col.f32.tf32.tf32.f32 "
        "{%0,%1,%2,%3}, {%4,%5,%6,%7}, {%8,%9}, {%0,%1,%2,%3};"
        : "+f"(d[0]), "+f"(d[1]), "+f"(d[2]), "+f"(d[3])
        : "r"(a0), "r"(a1), "r"(a2), "r"(a3), "r"(b0), "r"(b1));
}

// -------- prep (merged): zero counts, preset g_start, max init, W fragments ----
__global__ void k_prep(const int* __restrict__ batch,
                       const float* __restrict__ w0,
                       const float* __restrict__ w1,
                       const float* __restrict__ w2) {
    int i = blockIdx.x * blockDim.x + threadIdx.x;
    if (i < NN) {
        g_cnt[i] = 0;
        int b = batch[i];
        int bp = (i == 0) ? -1 : batch[i - 1];
        for (int g = bp + 1; g <= b; ++g) g_start[g] = i;
        if (batch[NN - 1] < NG && i == 0) {
            for (int g = batch[NN - 1] + 1; g <= NG; ++g) g_start[g] = NN;
        }
    }
    if (i == 0) g_start[NG] = NN;
    if (i < NHEAD) {
        g_maxs[i] = __int_as_float(0xff800000u);
        g_maxd[i] = __int_as_float(0xff800000u);
    }
    if (i < 3 * 8192) {
        int l = i >> 13, s = i & 8191;
        const float* W = (l == 0) ? w0 : (l == 1) ? w1 : w2;
        int lane = s & 31, ktG = (s >> 5) & 15, ntG = s >> 9;
        int n = ntG * 8 + (lane >> 2);
        int k0 = ktG * 8 + (lane & 3);
        float v0 = W[n * CATC + k0];
        float v1 = W[n * CATC + k0 + 4];
        uint4 f;
        f.x = tf32rn(v0);
        f.y = tf32rn(v1);
        f.z = tf32rn(v0 - __uint_as_float(f.x));
        f.w = tf32rn(v1 - __uint_as_float(f.y));
        g_wfrag[i] = f;
    }
}

// ------ TF32 tensor GEMM 3xTF32 (+bias)(+scores+max)(+norm)(+CSR tails) ---------
#define TG_SMEM ((128 * 132 + 384) * 4)

template <int ASEL, int DSEL, int WSEL, bool BIAS, bool SCORES, bool NORM, int TAIL>
__global__ void __launch_bounds__(256, 2)
k_tgemm(const float* __restrict__ Aext,
        const float* __restrict__ bias,
        const float* __restrict__ a_src,
        const float* __restrict__ a_dst,
        const int* __restrict__ batch,
        const int* __restrict__ ei) {
    extern __shared__ float sm[];
    int tid = threadIdx.x;

    if (TAIL != 0) {
        int tb = (int)blockIdx.x - GEMMB;
        if (tb >= 0) {
            int t = tb * 256 + tid;
            if (t < NE / 4) {
                if (TAIL == 1) {
                    int4 d4 = ((const int4*)(ei + NE))[t];
                    atomicAdd(&g_cnt[d4.x], 1);
                    atomicAdd(&g_cnt[d4.y], 1);
                    atomicAdd(&g_cnt[d4.z], 1);
                    atomicAdd(&g_cnt[d4.w], 1);
                } else {
                    int4 s4 = ((const int4*)ei)[t];
                    int4 d4 = ((const int4*)(ei + NE))[t];
                    g_csr[atomicAdd(&g_cursor[d4.x], 1)] = s4.x;
                    g_csr[atomicAdd(&g_cursor[d4.y], 1)] = s4.y;
                    g_csr[atomicAdd(&g_cursor[d4.z], 1)] = s4.z;
                    g_csr[atomicAdd(&g_cursor[d4.w], 1)] = s4.w;
                }
            }
            return;
        }
    }

    float* aT   = sm;                  // [128][132]
    float* sBia = sm + 128 * 132;
    float* sSrc = sBia + 128;
    float* sDst = sSrc + 128;

    const float* A = (ASEL == 0) ? Aext : g_bufX;

    int wid = tid >> 5, lane = tid & 31;
    int wm = wid >> 1, wn = wid & 1, gid = lane >> 2, tig = lane & 3;
    int row0 = blockIdx.x * 128;

    if (tid < 128) {
        if (BIAS) sBia[tid] = bias[tid];
        if (SCORES) { sSrc[tid] = a_src[tid]; sDst[tid] = a_dst[tid]; }
    }

#pragma unroll
    for (int i = 0; i < 16; i++) {
        int idx = tid + 256 * i;
        int r = idx >> 5, q = idx & 31;
        int grow = row0 + r;
        float4 v = make_float4(0.f, 0.f, 0.f, 0.f);
        if (grow < NN) {
            v = ((const float4*)A)[grow * 32 + q];
            if (NORM) {
                int g = batch[grow];
                float4 a4 = ((const float4*)g_nA)[g * 32 + q];
                float4 b4 = ((const float4*)g_nB)[g * 32 + q];
                v.x = fmaf(v.x, a4.x, b4.x);
                v.y = fmaf(v.y, a4.y, b4.y);
                v.z = fmaf(v.z, a4.z, b4.z);
                v.w = fmaf(v.w, a4.w, b4.w);
            }
        }
        *(float4*)&aT[r * 132 + q * 4] = v;
    }
    __syncthreads();

    float d[2][8][4];
#pragma unroll
    for (int mt = 0; mt < 2; mt++)
#pragma unroll
        for (int nt = 0; nt < 8; nt++)
#pragma unroll
            for (int f = 0; f < 4; f++) d[mt][nt][f] = 0.f;

    const uint4* wf = g_wfrag + WSEL * 8192;

#pragma unroll 4
    for (int ktG = 0; ktG < 16; ktG++) {
        uint4 bb[8];
#pragma unroll
        for (int nt = 0; nt < 8; nt++)
            bb[nt] = wf[(((wn * 8 + nt) << 4) + ktG) * 32 + lane];
        uint32_t aH[2][4], aL[2][4];
#pragma unroll
        for (int mt = 0; mt < 2; mt++) {
            int rb = wm * 32 + mt * 16 + gid;
            int c = ktG * 8 + tig;
            float v0 = aT[rb * 132 + c];
            float v1 = aT[(rb + 8) * 132 + c];
            float v2 = aT[rb * 132 + c + 4];
            float v3 = aT[(rb + 8) * 132 + c + 4];
            aH[mt][0] = tf32rn(v0); aL[mt][0] = tf32rn(v0 - __uint_as_float(aH[mt][0]));
            aH[mt][1] = tf32rn(v1); aL[mt][1] = tf32rn(v1 - __uint_as_float(aH[mt][1]));
            aH[mt][2] = tf32rn(v2); aL[mt][2] = tf32rn(v2 - __uint_as_float(aH[mt][2]));
            aH[mt][3] = tf32rn(v3); aL[mt][3] = tf32rn(v3 - __uint_as_float(aH[mt][3]));
        }
#pragma unroll
        for (int nt = 0; nt < 8; nt++)
#pragma unroll
            for (int mt = 0; mt < 2; mt++) {
                mma8(d[mt][nt], aH[mt][0], aH[mt][1], aH[mt][2], aH[mt][3], bb[nt].x, bb[nt].y);
                mma8(d[mt][nt], aH[mt][0], aH[mt][1], aH[mt][2], aH[mt][3], bb[nt].z, bb[nt].w);
                mma8(d[mt][nt], aL[mt][0], aL[mt][1], aL[mt][2], aL[mt][3], bb[nt].x, bb[nt].y);
            }
    }

    float sc[2][2][2][2];
    if (SCORES) {
#pragma unroll
        for (int a = 0; a < 2; a++)
#pragma unroll
            for (int b = 0; b < 2; b++)
#pragma unroll
                for (int c = 0; c < 2; c++) {
                    sc[a][b][c][0] = 0.f; sc[a][b][c][1] = 0.f;
                }
    }
#pragma unroll
    for (int mt = 0; mt < 2; mt++) {
        int r0 = row0 + wm * 32 + mt * 16 + gid;
#pragma unroll
        for (int nt = 0; nt < 8; nt++) {
            int c0 = wn * 64 + nt * 8 + 2 * tig;
            float v0 = d[mt][nt][0], v1 = d[mt][nt][1];
            float v2 = d[mt][nt][2], v3 = d[mt][nt][3];
            if (SCORES) {
                int hh = nt >> 2;
                float s0 = sSrc[c0], s1 = sSrc[c0 + 1];
                float t0 = sDst[c0], t1 = sDst[c0 + 1];
                sc[mt][0][hh][0] += v0 * s0 + v1 * s1;
                sc[mt][0][hh][1] += v0 * t0 + v1 * t1;
                sc[mt][1][hh][0] += v2 * s0 + v3 * s1;
                sc[mt][1][hh][1] += v2 * t0 + v3 * t1;
            }
            if (BIAS) {
                float b0 = sBia[c0], b1 = sBia[c0 + 1];
                v0 += b0; v1 += b1; v2 += b0; v3 += b1;
            }
            if (r0 < NN) {
                if (DSEL == 0) *(float2*)&g_bufX[r0 * CATC + c0] = make_float2(v0, v1);
                else           g_bufH16[r0 * 64 + (c0 >> 1)] = __floats2half2_rn(v0, v1);
            }
            if (r0 + 8 < NN) {
                if (DSEL == 0) *(float2*)&g_bufX[(r0 + 8) * CATC + c0] = make_float2(v2, v3);
                else           g_bufH16[(r0 + 8) * 64 + (c0 >> 1)] = __floats2half2_rn(v2, v3);
            }
        }
    }
    if (SCORES) {
#pragma unroll
        for (int a = 0; a < 2; a++)
#pragma unroll
            for (int b = 0; b < 2; b++)
#pragma unroll
                for (int c = 0; c < 2; c++)
#pragma unroll
                    for (int s = 0; s < 2; s++) {
                        float v = sc[a][b][c][s];
                        v += __shfl_xor_sync(0xffffffffu, v, 1);
                        v += __shfl_xor_sync(0xffffffffu, v, 2);
                        sc[a][b][c][s] = v;
                    }
        if (tig == 0) {
#pragma unroll
            for (int mt = 0; mt < 2; mt++)
#pragma unroll
                for (int rh = 0; rh < 2; rh++) {
                    int r = row0 + wm * 32 + mt * 16 + gid + rh * 8;
                    if (r < NN) {
#pragma unroll
                        for (int hh = 0; hh < 2; hh++) {
                            int head = wn * 2 + hh;
                            g_ssrc[r * 4 + head] = sc[mt][rh][hh][0];
                            g_sdst[r * 4 + head] = sc[mt][rh][hh][1];
                        }
                    }
                }
        }
#pragma unroll
        for (int hh = 0; hh < 2; hh++) {
            float ms = fmaxf(fmaxf(sc[0][0][hh][0], sc[0][1][hh][0]),
                             fmaxf(sc[1][0][hh][0], sc[1][1][hh][0]));
            float md = fmaxf(fmaxf(sc[0][0][hh][1], sc[0][1][hh][1]),
                             fmaxf(sc[1][0][hh][1], sc[1][1][hh][1]));
#pragma unroll
            for (int off = 4; off <= 16; off <<= 1) {
                ms = fmaxf(ms, __shfl_xor_sync(0xffffffffu, ms, off));
                md = fmaxf(md, __shfl_xor_sync(0xffffffffu, md, off));
            }
            if (lane == 0) {
                atomicMaxF(&g_maxs[wn * 2 + hh], ms);
                atomicMaxF(&g_maxd[wn * 2 + hh], md);
            }
        }
    }
}

// ---------------- scan stage 1 ----------------
__global__ void k_scan1() {
    __shared__ int wsum[8];
    int b = blockIdx.x, t = threadIdx.x;
    int idx0 = b * 1024 + t * 4;
    int v[4];
#pragma unroll
    for (int k = 0; k < 4; k++) v[k] = (idx0 + k < NN) ? g_cnt[idx0 + k] : 0;
    int s = v[0] + v[1] + v[2] + v[3];
    int lane = t & 31, wid = t >> 5;
    int incl = s;
#pragma unroll
    for (int off = 1; off <= 16; off <<= 1) {
        int nv = __shfl_up_sync(0xffffffffu, incl, off);
        if (lane >= off) incl += nv;
    }
    if (lane == 31) wsum[wid] = incl;
    __syncthreads();
    if (t == 0) {
        int r = 0;
#pragma unroll
        for (int w = 0; w < 8; w++) { int x = wsum[w]; wsum[w] = r; r += x; }
    }
    __syncthreads();
    int excl = incl - s + wsum[wid];
    int run = excl;
#pragma unroll
    for (int k = 0; k < 4; k++) {
        if (idx0 + k < NN) g_off[idx0 + k] = run;
        run += v[k];
    }
    if (t == 255) g_bsum[b] = excl + s;
}

// ---------------- scan stage 2+3 merged ----------------
__global__ void k_scan23() {
    __shared__ int sOff;
    int i = blockIdx.x * blockDim.x + threadIdx.x;
    if (threadIdx.x == 0) {
        int grp = (blockIdx.x * blockDim.x) >> 10;
        int r = 0;
        for (int b = 0; b < grp; b++) r += g_bsum[b];
        sOff = r;
    }
    __syncthreads();
    if (i < NN) {
        int o = g_off[i] + sOff;
        g_off[i] = o;
        g_cursor[i] = o;
    }
    if (i == 0) {
        int r = 0;
        for (int b = 0; b < SCAN_B; b++) r += g_bsum[b];
        g_off[NN] = r;
    }
}

// ---------------- fused GAT aggregate (warp per dst, fp16 gather) ----------------
__global__ void k_gat(const float* __restrict__ bias) {
    int n = (blockIdx.x * blockDim.x + threadIdx.x) >> 5;
    if (n >= NN) return;
    int lane = threadIdx.x & 31;
    int head = lane >> 3;

    float shift = lrelu(g_maxs[head] + g_maxd[head]);
    float sd = g_sdst[n * 4 + head];

    float p = __expf(lrelu(g_ssrc[n * 4 + head] + sd) - shift);
    uint2 hs = ((const uint2*)g_bufH16)[n * 32 + lane];
    float2 s01 = __half22float2(*(__half2*)&hs.x);
    float2 s23 = __half22float2(*(__half2*)&hs.y);
    float ax = s01.x * p, ay = s01.y * p, az = s23.x * p, aw = s23.y * p;
    float den = p;

    int o0 = g_off[n], o1 = g_off[n + 1];
    for (int base = o0; base < o1; base += 32) {
        int id = 0;
        if (base + lane < o1) id = g_csr[base + lane];
        int cnt = min(32, o1 - base);
#pragma unroll 4
        for (int j = 0; j < cnt; j++) {
            int src = __shfl_sync(0xffffffffu, id, j);
            float ss = g_ssrc[src * 4 + head];
            float pe = __expf(lrelu(ss + sd) - shift);
            uint2 hraw = ((const uint2*)g_bufH16)[src * 32 + lane];
            float2 f01 = __half22float2(*(__half2*)&hraw.x);
            float2 f23 = __half22float2(*(__half2*)&hraw.y);
            ax += f01.x * pe; ay += f01.y * pe;
            az += f23.x * pe; aw += f23.y * pe;
            den += pe;
        }
    }
    float inv = 1.f / den;
    float4 b = ((const float4*)bias)[lane];
    float4 o;
    o.x = eluf(ax * inv + b.x);
    o.y = eluf(ay * inv + b.y);
    o.z = eluf(az * inv + b.z);
    o.w = eluf(aw * inv + b.w);
    ((float4*)g_bufX)[n * 32 + lane] = o;
}

// -------- layer-1 GraphNorm stats -> affine A',B' (+max reset for layer 2) ------
__global__ void k_norm_stats(const float* __restrict__ nw,
                             const float* __restrict__ nb,
                             const float* __restrict__ nms) {
    __shared__ float sh[256], sh2[256];
    int g = blockIdx.x, q = blockIdx.y;
    if (g == 0 && q == 0 && threadIdx.x < NHEAD) {
        g_maxs[threadIdx.x] = __int_as_float(0xff800000u);
        g_maxd[threadIdx.x] = __int_as_float(0xff800000u);
    }
    int tc = threadIdx.x & 31, tr = threadIdx.x >> 5;
    int c = q * 32 + tc;
    int s0 = g_start[g], s1 = g_start[g + 1];
    float s = 0.f, s2 = 0.f;
    for (int r = s0 + tr; r < s1; r += 8) {
        float v = g_bufX[r * CATC + c];
        s += v; s2 += v * v;
    }
    sh[threadIdx.x] = s; sh2[threadIdx.x] = s2;
    __syncthreads();
    for (int off = 128; off >= 32; off >>= 1) {
        if (threadIdx.x < off) {
            sh[threadIdx.x] += sh[threadIdx.x + off];
            sh2[threadIdx.x] += sh2[threadIdx.x + off];
        }
        __syncthreads();
    }
    if (threadIdx.x < 32) {
        int cnt = s1 - s0;
        float A = 0.f, B = nb[c];
        if (cnt > 0) {
            float fc = (float)cnt;
            float mean = sh[tc] / fc;
            float ms = nms[c];
            float var = sh2[tc] / fc - (2.f * ms - ms * ms) * mean * mean;
            float inv = rsqrtf(var + EPSN);
            A = nw[c] * inv;
            B = nb[c] - A * ms * mean;
        }
        g_nA[g * CATC + c] = A;
        g_nB[g * CATC + c] = B;
    }
}

// -------- layer-2 GraphNorm stats + fused max pool (merged; grid (G,4)) ---------
__global__ void k_norm_pool(const float* __restrict__ nw,
                            const float* __restrict__ nb,
                            const float* __restrict__ nms) {
    __shared__ float sh[256], sh2[256];
    __shared__ float shA[32], shB[32];
    int g = blockIdx.x, q = blockIdx.y;
    int tc = threadIdx.x & 31, tr = threadIdx.x >> 5;
    int c = q * 32 + tc;
    int s0 = g_start[g], s1 = g_start[g + 1];
    float s = 0.f, s2 = 0.f;
    for (int r = s0 + tr; r < s1; r += 8) {
        float v = g_bufX[r * CATC + c];
        s += v; s2 += v * v;
    }
    sh[threadIdx.x] = s; sh2[threadIdx.x] = s2;
    __syncthreads();
    for (int off = 128; off >= 32; off >>= 1) {
        if (threadIdx.x < off) {
            sh[threadIdx.x] += sh[threadIdx.x + off];
            sh2[threadIdx.x] += sh2[threadIdx.x + off];
        }
        __syncthreads();
    }
    if (threadIdx.x < 32) {
        int cnt = s1 - s0;
        float A = 0.f, B = nb[c];
        if (cnt > 0) {
            float fc = (float)cnt;
            float mean = sh[tc] / fc;
            float ms = nms[c];
            float var = sh2[tc] / fc - (2.f * ms - ms * ms) * mean * mean;
            float inv = rsqrtf(var + EPSN);
            A = nw[c] * inv;
            B = nb[c] - A * ms * mean;
        }
        shA[tc] = A; shB[tc] = B;
    }
    __syncthreads();
    // second pass (L2-hot): apply affine and max-pool
    float a = shA[tc], b = shB[tc];
    float m = __int_as_float(0xff800000u);
    for (int r = s0 + tr; r < s1; r += 8)
        m = fmaxf(m, fmaf(g_bufX[r * CATC + c], a, b));
    sh[threadIdx.x] = m;
    __syncthreads();
    for (int off = 128; off >= 32; off >>= 1) {
        if (threadIdx.x < off) sh[threadIdx.x] = fmaxf(sh[threadIdx.x], sh[threadIdx.x + off]);
        __syncthreads();
    }
    if (threadIdx.x < 32) g_pool[g * CATC + c] = sh[tc];
}

// ---------------- final fc ----------------
__global__ void k_fc(const float* __restrict__ fw, const float* __restrict__ fb,
                     float* __restrict__ out) {
    int g = blockIdx.x, o = threadIdx.x;
    float acc = fb[o];
#pragma unroll
    for (int c = 0; c < CATC; c += 4) {
        float4 p  = *(const float4*)&g_pool[g * CATC + c];
        float4 wv = *(const float4*)&fw[o * CATC + c];
        acc += p.x * wv.x + p.y * wv.y + p.z * wv.z + p.w * wv.w;
    }
    out[g * OUTD + o] = acc;
}

// ---------------- launch ----------------
extern "C" void kernel_launch(void* const* d_in, const int* in_sizes, int n_in,
                              void* d_out, int out_size) {
    const float* x     = (const float*)d_in[0];
    const int*   ei    = (const int*)d_in[1];
    const int*   batch = (const int*)d_in[2];
    const float* enc_w = (const float*)d_in[3];
    const float* enc_b = (const float*)d_in[4];
    const float* w1    = (const float*)d_in[5];
    const float* as1   = (const float*)d_in[6];
    const float* ad1   = (const float*)d_in[7];
    const float* b1    = (const float*)d_in[8];
    const float* n1w   = (const float*)d_in[9];
    const float* n1b   = (const float*)d_in[10];
    const float* n1ms  = (const float*)d_in[11];
    const float* w2    = (const float*)d_in[12];
    const float* as2   = (const float*)d_in[13];
    const float* ad2   = (const float*)d_in[14];
    const float* b2    = (const float*)d_in[15];
    const float* n2w   = (const float*)d_in[16];
    const float* n2b   = (const float*)d_in[17];
    const float* n2ms  = (const float*)d_in[18];
    const float* fw    = (const float*)d_in[19];
    const float* fb    = (const float*)d_in[20];
    float* out = (float*)d_out;

    cudaFuncSetAttribute(k_tgemm<0, 0, 0, true, false, false, 1>,
                         cudaFuncAttributeMaxDynamicSharedMemorySize, TG_SMEM);
    cudaFuncSetAttribute(k_tgemm<1, 1, 1, false, true, false, 2>,
                         cudaFuncAttributeMaxDynamicSharedMemorySize, TG_SMEM);
    cudaFuncSetAttribute(k_tgemm<1, 1, 2, false, true, true, 0>,
                         cudaFuncAttributeMaxDynamicSharedMemorySize, TG_SMEM);

    const int gatBlocks = (NN * 32 + 255) / 256;

    // prep (merged) — one launch
    k_prep<<<(NN + 255) / 256, 256>>>(batch, enc_w, w1, w2);

    // encoder GEMM + degree-count tail blocks (overlapped)
    k_tgemm<0, 0, 0, true, false, false, 1><<<GEMMB + EDGE4B, 256, TG_SMEM>>>(
        x, enc_b, nullptr, nullptr, nullptr, ei);

    // prefix scan (merged stages 2+3)
    k_scan1<<<SCAN_B, 256>>>();
    k_scan23<<<(NN + 255) / 256, 256>>>();

    // ---- layer 1 GEMM (scores + fused max) + CSR-fill tail blocks ----
    k_tgemm<1, 1, 1, false, true, false, 2><<<GEMMB + EDGE4B, 256, TG_SMEM>>>(
        nullptr, nullptr, as1, ad1, nullptr, ei);
    k_gat<<<gatBlocks, 256>>>(b1);
    k_norm_stats<<<dim3(NG, 4), 256>>>(n1w, n1b, n1ms);

    // ---- layer 2 (A-staging applies norm1 affine) ----
    k_tgemm<1, 1, 2, false, true, true, 0><<<GEMMB, 256, TG_SMEM>>>(
        nullptr, nullptr, as2, ad2, batch, nullptr);
    k_gat<<<gatBlocks, 256>>>(b2);

    // ---- layer-2 norm stats + pool (merged) + fc ----
    k_norm_pool<<<dim3(NG, 4), 256>>>(n2w, n2b, n2ms);
    k_fc<<<NG, OUTD>>>(fw, fb, out);
}